// round 9
// baseline (speedup 1.0000x reference)
#include <cuda_runtime.h>
#include <cstdint>

// Pink noise: 6-pole diagonal IIR + 1-sample delay, exact segment scan.
// white[B, L] -> pink[B, L], L=65536, one block per channel.
//
// v6: register-direct, NO smem data tile. A thread's 32-sample chunk is
// exactly one 128B line, so per-thread LDG.128 is sector-efficient; pass B
// re-reads the same line from L1 (128KB/SM working set fits) and stores
// output directly with STG.128 (L2 merges 16B writes into full lines).
// Only smem: 2x(warpT+lastw) scan exchange, double-buffered by segment
// parity -> ONE __syncthreads per segment.

#define NT      512
#define SEG     16384
#define NSEG    4
#define LROW    65536
#define NW      16

typedef unsigned long long ull;

__device__ __forceinline__ ull pk2(float lo, float hi) {
    ull r; asm("mov.b64 %0, {%1, %2};" : "=l"(r) : "f"(lo), "f"(hi)); return r;
}
__device__ __forceinline__ void upk2(ull v, float& lo, float& hi) {
    asm("mov.b64 {%0, %1}, %2;" : "=f"(lo), "=f"(hi) : "l"(v));
}
__device__ __forceinline__ ull ffma2(ull a, ull b, ull c) {
    ull d; asm("fma.rn.f32x2 %0, %1, %2, %3;" : "=l"(d) : "l"(a), "l"(b), "l"(c)); return d;
}
__device__ __forceinline__ ull fmul2(ull a, ull b) {
    ull d; asm("mul.rn.f32x2 %0, %1, %2;" : "=l"(d) : "l"(a), "l"(b)); return d;
}

__global__ void __launch_bounds__(NT, 2)
pink_kernel(const float* __restrict__ white, float* __restrict__ out) {
    __shared__ float warpT[2][NW][6];
    __shared__ float lastw[2][NW];

    const float A0 = 0.99886f, A1 = 0.99332f, A2 = 0.969f,
                A3 = 0.8665f,  A4 = 0.55f,    A5 = -0.7616f;
    const float OC0 = 0.11f * 0.0555179f, OC1 = 0.11f * 0.0750759f,
                OC2 = 0.11f * 0.153852f,  OC3 = 0.11f * 0.3104856f,
                OC4 = 0.11f * 0.5329522f, OC5 = 0.11f * -0.016898f;
    const float OB6 = 0.11f * 0.115926f, ODIR = 0.11f * 0.5362f;

    const int tid  = threadIdx.x;
    const int lane = tid & 31;
    const int wid  = tid >> 5;
    const float* wrow = white + (size_t)blockIdx.x * LROW;
    float*       orow = out   + (size_t)blockIdx.x * LROW;

    const ull A01 = pk2(A0, A1), A23 = pk2(A2, A3), A45 = pk2(A4, A5);
    const ull C01 = pk2(OC0, OC1), C23 = pk2(OC2, OC3), C45 = pk2(OC4, OC5);
    const ull ODB = pk2(ODIR, OB6);

    // Power tables: m = a^32, mlane = m^lane, m32w = (m^32)^wid, d512 = m^512.
    float m[6], mlane[6], m32w[6], d512[6];
    {
        const float a[6] = {A0, A1, A2, A3, A4, A5};
#pragma unroll
        for (int i = 0; i < 6; i++) {
            float t = a[i];
#pragma unroll
            for (int s = 0; s < 5; s++) t *= t;
            m[i] = t;                                  // a^32
            float b = t, r = 1.f; int e = lane;
#pragma unroll
            for (int s = 0; s < 5; s++) { if (e & 1) r *= b; b *= b; e >>= 1; }
            mlane[i] = r;                              // b == m^32 now
            float b2 = b, r2 = 1.f; int e2 = wid;
#pragma unroll
            for (int s = 0; s < 4; s++) { if (e2 & 1) r2 *= b2; b2 *= b2; e2 >>= 1; }
            m32w[i] = r2;
            float d = m[i];
#pragma unroll
            for (int sq = 0; sq < 9; sq++) d *= d;     // a^16384
            d512[i] = d;
        }
    }

    float segState[6] = {0.f, 0.f, 0.f, 0.f, 0.f, 0.f};
    float w_carry = 0.f;

#pragma unroll 1
    for (int s = 0; s < NSEG; s++) {
        const int p = s & 1;
        const float* wseg = wrow + (size_t)s * SEG + tid * 32;

        // ---------------- Pass A: chunk particular state (gmem reads) --------
        ull U01 = 0ull, U23 = 0ull, U45 = 0ull;
        float w31 = 0.f;
#pragma unroll
        for (int q = 0; q < 8; q++) {
            float4 wv = __ldg(reinterpret_cast<const float4*>(wseg) + q);
            float ws[4] = {wv.x, wv.y, wv.z, wv.w};
#pragma unroll
            for (int c = 0; c < 4; c++) {
                ull W = pk2(ws[c], ws[c]);
                U01 = ffma2(A01, U01, W);
                U23 = ffma2(A23, U23, W);
                U45 = ffma2(A45, U45, W);
            }
            if (q == 7) w31 = wv.w;
        }

        // Prefetch next segment's chunk (one 128B line per thread).
        if (s + 1 < NSEG)
            asm volatile("prefetch.global.L2 [%0];" :: "l"(wseg + SEG));

        // ---------------- Block scan over chunk states ----------------
        float pv[6];
        upk2(U01, pv[0], pv[1]); upk2(U23, pv[2], pv[3]); upk2(U45, pv[4], pv[5]);
        float mult[6];
#pragma unroll
        for (int i = 0; i < 6; i++) mult[i] = m[i];
#pragma unroll
        for (int o = 1; o < 32; o <<= 1) {
#pragma unroll
            for (int i = 0; i < 6; i++) {
                float up = __shfl_up_sync(0xffffffffu, pv[i], o);
                if (lane >= o) pv[i] = fmaf(mult[i], up, pv[i]);
                mult[i] *= mult[i];
            }
        }
        // mult == m^32
        float excl[6];
#pragma unroll
        for (int i = 0; i < 6; i++) {
            float e = __shfl_up_sync(0xffffffffu, pv[i], 1);
            excl[i] = (lane == 0) ? 0.f : e;
        }
        if (lane == 31) {
#pragma unroll
            for (int i = 0; i < 6; i++) warpT[p][wid][i] = pv[i];
            lastw[p][wid] = w31;
        }
        __syncthreads();                       // the ONLY barrier per segment

        // Redundant all-warp combine over the 16 warp totals.
        float E[6], tot[6];
        {
            float t6[6], cm[6];
#pragma unroll
            for (int i = 0; i < 6; i++) {
                t6[i] = (lane < NW) ? warpT[p][lane][i] : 0.f;
                cm[i] = mult[i];               // m^32
            }
#pragma unroll
            for (int o = 1; o < NW; o <<= 1) {
#pragma unroll
                for (int i = 0; i < 6; i++) {
                    float up = __shfl_up_sync(0xffffffffu, t6[i], o);
                    if (lane >= o) t6[i] = fmaf(cm[i], up, t6[i]);
                    cm[i] *= cm[i];
                }
            }
#pragma unroll
            for (int i = 0; i < 6; i++) {
                float pw = __shfl_sync(0xffffffffu, t6[i], (wid > 0) ? (wid - 1) : 0);
                if (wid == 0) pw = 0.f;
                tot[i] = __shfl_sync(0xffffffffu, t6[i], NW - 1);
                E[i] = fmaf(mlane[i], fmaf(m32w[i], segState[i], pw), excl[i]);
            }
        }

        // b6 delayed-white at the chunk boundary.
        float pwu = __shfl_up_sync(0xffffffffu, w31, 1);
        float prev_w;
        if (lane > 0)      prev_w = pwu;
        else if (wid > 0)  prev_w = lastw[p][wid - 1];
        else               prev_w = w_carry;
        w_carry = lastw[p][NW - 1];

#pragma unroll
        for (int i = 0; i < 6; i++)
            segState[i] = fmaf(d512[i], segState[i], tot[i]);

        // ---------------- Pass B: exact recompute (L1 hits), direct STG ------
        U01 = pk2(E[0], E[1]); U23 = pk2(E[2], E[3]); U45 = pk2(E[4], E[5]);
        float* oseg = orow + (size_t)s * SEG + tid * 32;
#pragma unroll
        for (int q = 0; q < 8; q++) {
            float4 wv = __ldg(reinterpret_cast<const float4*>(wseg) + q);
            float ws[4] = {wv.x, wv.y, wv.z, wv.w};
            float o4[4];
#pragma unroll
            for (int c = 0; c < 4; c++) {
                float w = ws[c];
                ull W = pk2(w, w);
                U01 = ffma2(A01, U01, W);
                U23 = ffma2(A23, U23, W);
                U45 = ffma2(A45, U45, W);
                ull P = ffma2(C01, U01, ffma2(C23, U23, fmul2(C45, U45)));
                ull T2 = ffma2(ODB, pk2(w, prev_w), P);
                float tlo, thi; upk2(T2, tlo, thi);
                o4[c] = tlo + thi;
                prev_w = w;
            }
            *(reinterpret_cast<float4*>(oseg) + q) = make_float4(o4[0], o4[1], o4[2], o4[3]);
        }
    }
}

extern "C" void kernel_launch(void* const* d_in, const int* in_sizes, int n_in,
                              void* d_out, int out_size) {
    const float* white = (const float*)d_in[0];
    float* out = (float*)d_out;
    int B = out_size / LROW;
    pink_kernel<<<B, NT>>>(white, out);
}